// round 2
// baseline (speedup 1.0000x reference)
#include <cuda_runtime.h>
#include <math.h>

// Problem constants
constexpr int FH   = 96;          // feature map height (axis 1, "y")
constexpr int FW   = 96;          // feature map width  (axis 2, "x")
constexpr int FC   = 512;         // channels
constexpr int FB   = 16;          // batch
constexpr int NROI = 32;
constexpr int NREG = 50;          // 1 + 4 + 9 + 36
constexpr int C4   = FC / 4;      // float4 channels = 128

// Region table: per (roi, region) -> x1, x2, y1, y2
__device__ int4 d_regions[NROI * NREG];

// ---------------------------------------------------------------------------
// Kernel A: compute region boundaries with EXACT Python-double semantics.
//   cl = h / p   (governs x axis in the reference, quirk replicated)
//   rl = w / p   (governs y axis)
//   x1 = int(round(x + ix*cl)); x2 = int(round((x + ix*cl) + cl))
// round() is banker's rounding -> rint() in default RN mode.
// __dmul_rn/__dadd_rn prevent FMA contraction from perturbing .5 boundaries.
// ---------------------------------------------------------------------------
__global__ void compute_regions_kernel(const int* __restrict__ rois) {
    int r = blockIdx.x * blockDim.x + threadIdx.x;
    if (r >= NROI * NREG) return;

    int roi = r / NREG;
    int k   = r % NREG;

    int P, off;
    if      (k < 1)  { P = 1; off = 0; }
    else if (k < 5)  { P = 2; off = 1; }
    else if (k < 14) { P = 3; off = 5; }
    else             { P = 6; off = 14; }
    int idx = k - off;
    int ix  = idx / P;
    int jy  = idx % P;

    double x = (double)rois[roi * 4 + 0];
    double y = (double)rois[roi * 4 + 1];
    double w = (double)rois[roi * 4 + 2];
    double h = (double)rois[roi * 4 + 3];

    double cl = h / (double)P;   // x-axis step (reference quirk)
    double rl = w / (double)P;   // y-axis step

    double tx = __dadd_rn(x, __dmul_rn((double)ix, cl));
    int x1 = (int)rint(tx);
    int x2 = (int)rint(__dadd_rn(tx, cl));

    double ty = __dadd_rn(y, __dmul_rn((double)jy, rl));
    int y1 = (int)rint(ty);
    int y2 = (int)rint(__dadd_rn(ty, rl));

    // Safety clamps (reference data never exceeds bounds: x+h <= 94 < 96)
    x1 = max(0, min(FW, x1));
    x2 = max(0, min(FW, x2));
    y1 = max(0, min(FH, y1));
    y2 = max(0, min(FH, y2));

    d_regions[r] = make_int4(x1, x2, y1, y2);
}

__device__ __forceinline__ void vmax4(float4& a, const float4 b) {
    a.x = fmaxf(a.x, b.x);
    a.y = fmaxf(a.y, b.y);
    a.z = fmaxf(a.z, b.z);
    a.w = fmaxf(a.w, b.w);
}

// ---------------------------------------------------------------------------
// Per-pool compute: one (roi, pool, batch) per block; thread c owns 4 channels.
// Region (ix, jy): x-range depends only on ix, y-range only on jy.
// Scan each y band once, keep P accumulators (one per ix segment) in registers.
// ---------------------------------------------------------------------------
template <int P>
__device__ __forceinline__ void pool_compute(const float4* __restrict__ fmb,
                                             const int4*  __restrict__ regs,
                                             float4*      __restrict__ outb,
                                             int c) {
    int xs1[P], xs2[P], ys1[P], ys2[P];
#pragma unroll
    for (int i = 0; i < P; i++) {          // region (ix=i, jy=0) -> idx i*P
        int4 q = regs[i * P];
        xs1[i] = q.x; xs2[i] = q.y;
    }
#pragma unroll
    for (int j = 0; j < P; j++) {          // region (ix=0, jy=j) -> idx j
        int4 q = regs[j];
        ys1[j] = q.z; ys2[j] = q.w;
    }

#pragma unroll
    for (int j = 0; j < P; j++) {
        float4 acc[P];
#pragma unroll
        for (int i = 0; i < P; i++)
            acc[i] = make_float4(-INFINITY, -INFINITY, -INFINITY, -INFINITY);

        for (int y = ys1[j]; y < ys2[j]; y++) {
            const float4* row = fmb + (size_t)y * FW * C4 + c;
#pragma unroll
            for (int i = 0; i < P; i++) {
                int xe = xs2[i];
#pragma unroll 4
                for (int x = xs1[i]; x < xe; x++) {
                    float4 v = __ldg(row + (size_t)x * C4);
                    vmax4(acc[i], v);
                }
            }
        }
#pragma unroll
        for (int i = 0; i < P; i++)
            outb[(size_t)(i * P + j) * C4 + c] = acc[i];
    }
}

// Grid: NROI * 4 * FB blocks, roi-major so a ROI's 64 blocks co-run (L2 reuse).
__global__ void __launch_bounds__(128)
roi_pool_kernel(const float* __restrict__ fm, float* __restrict__ out) {
    int bid  = blockIdx.x;
    int roi  = bid >> 6;         // 64 blocks per roi
    int rem  = bid & 63;
    int pool = rem >> 4;         // 4 pools
    int b    = rem & 15;         // 16 batches
    int c    = threadIdx.x;      // float4-channel 0..127

    const float4* fmb  = (const float4*)fm + (size_t)b * FH * FW * C4;
    float4*       outb = (float4*)out + ((size_t)b * NROI * NREG + (size_t)roi * NREG) * C4;
    const int4*   regs = d_regions + roi * NREG;

    switch (pool) {
        case 0: pool_compute<1>(fmb, regs,      outb,                 c); break;
        case 1: pool_compute<2>(fmb, regs + 1,  outb + (size_t)1  * C4, c); break;
        case 2: pool_compute<3>(fmb, regs + 5,  outb + (size_t)5  * C4, c); break;
        default:pool_compute<6>(fmb, regs + 14, outb + (size_t)14 * C4, c); break;
    }
}

extern "C" void kernel_launch(void* const* d_in, const int* in_sizes, int n_in,
                              void* d_out, int out_size) {
    const float* fm   = (const float*)d_in[0];
    const int*   rois = (const int*)d_in[1];
    float*       out  = (float*)d_out;

    compute_regions_kernel<<<(NROI * NREG + 255) / 256, 256>>>(rois);
    roi_pool_kernel<<<NROI * 4 * FB, 128>>>(fm, out);
}

// round 4
// speedup vs baseline: 2.4352x; 2.4352x over previous
#include <cuda_runtime.h>
#include <math.h>

// Problem constants
constexpr int FH   = 96;
constexpr int FW   = 96;
constexpr int FC   = 512;
constexpr int FB   = 16;
constexpr int NROI = 32;
constexpr int NREG = 50;          // 1 + 4 + 9 + 36
constexpr int C4   = FC / 4;      // 128 float4 channels

constexpr int CH   = 8;           // rows per y-chunk
constexpr int NCK  = FH / CH;     // 12 chunks cover all absolute rows

// Region table: per (roi, region) -> x1, x2, y1, y2
__device__ int4 d_regions[NROI * NREG];

// ---------------------------------------------------------------------------
// Exact Python-double region boundaries (identical to the PASSING R1 kernel).
//   cl = h / p governs x axis (reference quirk), rl = w / p governs y axis.
//   round() = banker's rounding -> rint(); forced RN double ops (no FMA drift).
// ---------------------------------------------------------------------------
__global__ void compute_regions_kernel(const int* __restrict__ rois) {
    int r = blockIdx.x * blockDim.x + threadIdx.x;
    if (r >= NROI * NREG) return;

    int roi = r / NREG;
    int k   = r % NREG;

    int P, off;
    if      (k < 1)  { P = 1; off = 0; }
    else if (k < 5)  { P = 2; off = 1; }
    else if (k < 14) { P = 3; off = 5; }
    else             { P = 6; off = 14; }
    int idx = k - off;
    int ix  = idx / P;
    int jy  = idx % P;

    double x = (double)rois[roi * 4 + 0];
    double y = (double)rois[roi * 4 + 1];
    double w = (double)rois[roi * 4 + 2];
    double h = (double)rois[roi * 4 + 3];

    double cl = h / (double)P;   // x-axis step (reference quirk)
    double rl = w / (double)P;   // y-axis step

    double tx = __dadd_rn(x, __dmul_rn((double)ix, cl));
    int x1 = (int)rint(tx);
    int x2 = (int)rint(__dadd_rn(tx, cl));

    double ty = __dadd_rn(y, __dmul_rn((double)jy, rl));
    int y1 = (int)rint(ty);
    int y2 = (int)rint(__dadd_rn(ty, rl));

    x1 = max(0, min(FW, x1));
    x2 = max(0, min(FW, x2));
    y1 = max(0, min(FH, y1));
    y2 = max(0, min(FH, y2));

    d_regions[r] = make_int4(x1, x2, y1, y2);
}

// Monotone fp32 <-> uint32 mapping so atomicMax(uint) == fmax (bit-exact).
__device__ __forceinline__ unsigned int encf(float f) {
    unsigned int u = __float_as_uint(f);
    return (u & 0x80000000u) ? ~u : (u | 0x80000000u);
}
__device__ __forceinline__ float decf(unsigned int u) {
    return __uint_as_float((u & 0x80000000u) ? (u & 0x7FFFFFFFu) : ~u);
}

__global__ void init_out_kernel(unsigned int* __restrict__ out, int n4) {
    int i = blockIdx.x * blockDim.x + threadIdx.x;
    if (i < n4) {
        // enc(-inf) = 0x007FFFFF
        ((uint4*)out)[i] = make_uint4(0x007FFFFFu, 0x007FFFFFu, 0x007FFFFFu, 0x007FFFFFu);
    }
}

__global__ void decode_out_kernel(unsigned int* __restrict__ out, int n4) {
    int i = blockIdx.x * blockDim.x + threadIdx.x;
    if (i < n4) {
        uint4 v = ((uint4*)out)[i];
        float4 f = make_float4(decf(v.x), decf(v.y), decf(v.z), decf(v.w));
        ((float4*)out)[i] = f;
    }
}

__device__ __forceinline__ void vmax4(float4& a, const float4 b) {
    a.x = fmaxf(a.x, b.x);
    a.y = fmaxf(a.y, b.y);
    a.z = fmaxf(a.z, b.z);
    a.w = fmaxf(a.w, b.w);
}

// ---------------------------------------------------------------------------
// One block = (batch, y-chunk, roi, pool). Each region (i,j) of the pool level
// is computed with its OWN exact [x1,x2) x [y1,y2) intersected with the chunk
// rows — identical semantics to the reference (overlaps/gaps between regions
// are irrelevant: each region scans its own box). Partials merged by atomicMax.
// Block order: batch slowest, then chunk -> co-resident blocks share one
// ~1.5MB row stripe of one image (L2-friendly).
// ---------------------------------------------------------------------------
__global__ void __launch_bounds__(128)
roi_pool_atomic(const float* __restrict__ fm, unsigned int* __restrict__ out) {
    int bid  = blockIdx.x;
    int pool = bid & 3;
    int roi  = (bid >> 2) & 31;
    int rest = bid >> 7;
    int ck   = rest % NCK;
    int b    = rest / NCK;

    int P   = (pool == 0) ? 1 : (pool == 1) ? 2 : (pool == 2) ? 3 : 6;
    int off = (pool == 0) ? 0 : (pool == 1) ? 1 : (pool == 2) ? 5 : 14;

    int yc0 = ck * CH;
    int yc1 = yc0 + CH;
    int c   = threadIdx.x;        // float4-channel 0..127

    const int4*   regs = d_regions + roi * NREG + off;
    const float4* fmb  = (const float4*)fm + (size_t)b * FH * FW * C4 + c;
    unsigned int* outb = out + (((size_t)(b * NROI + roi) * NREG + off) << 9) + c * 4;

    const float4 NEG = make_float4(-INFINITY, -INFINITY, -INFINITY, -INFINITY);

    for (int j = 0; j < P; j++) {
        int4 rj = __ldg(&regs[j]);                 // region (ix=0, jy=j): y-range
        int y1 = max(rj.z, yc0), y2 = min(rj.w, yc1);
        if (y1 >= y2) continue;

        for (int i = 0; i < P; i++) {
            int4 ri = __ldg(&regs[i * P]);         // region (ix=i, jy=0): x-range
            int x1 = ri.x, x2 = ri.y;

            float4 a0 = NEG, a1 = NEG;             // dual acc: halve fmax chain
            for (int y = y1; y < y2; y++) {
                const float4* row = fmb + (size_t)y * FW * C4;
                int x = x1;
                for (; x + 2 <= x2; x += 2) {
                    vmax4(a0, __ldg(row + (size_t)x * C4));
                    vmax4(a1, __ldg(row + (size_t)(x + 1) * C4));
                }
                if (x < x2) vmax4(a0, __ldg(row + (size_t)x * C4));
            }
            vmax4(a0, a1);

            unsigned int* o = outb + ((size_t)(i * P + j) << 9);
            atomicMax(o + 0, encf(a0.x));
            atomicMax(o + 1, encf(a0.y));
            atomicMax(o + 2, encf(a0.z));
            atomicMax(o + 3, encf(a0.w));
        }
    }
}

extern "C" void kernel_launch(void* const* d_in, const int* in_sizes, int n_in,
                              void* d_out, int out_size) {
    const float* fm   = (const float*)d_in[0];
    const int*   rois = (const int*)d_in[1];
    unsigned int* out = (unsigned int*)d_out;

    int n4 = out_size / 4;                         // 3,276,800 uint4s
    int ib = (n4 + 255) / 256;

    init_out_kernel<<<ib, 256>>>(out, n4);
    compute_regions_kernel<<<(NROI * NREG + 255) / 256, 256>>>(rois);
    roi_pool_atomic<<<FB * NCK * NROI * 4, 128>>>(fm, out);
    decode_out_kernel<<<ib, 256>>>(out, n4);
}